// round 16
// baseline (speedup 1.0000x reference)
#include <cuda_runtime.h>
#include <cuda_fp16.h>
#include <stdint.h>
#include <math.h>

#define B_  2
#define N_  16384
#define M_  2048
#define D_  256
#define R_  (B_*N_)
#define RQ_ (B_*M_)
#define NSPLIT 4
#define KR_ (N_/NSPLIT)          // 4096 contraction per wv split
#define NMT 16                   // number of m-tiles (M_/128)
#define STAGE 32768              // A0(8K) A1(8K) B0(8K) B1(8K)  (K-chunk 64)
#define DYN_SMEM (3*STAGE)       // 96 KB

// ======================= device scratch =====================================
__device__ __align__(16) float  g_r[R_*3];
__device__ __align__(16) __half g_ph [(size_t)R_*D_];
__device__ __align__(16) __half g_vfh[(size_t)RQ_*D_];
__device__ __align__(16) __half g_wqT[D_*D_], g_wkT[D_*D_], g_wvT[D_*D_];
__device__ __align__(16) __half g_qh [(size_t)RQ_*D_];        // pre-scaled by 1/16
__device__ __align__(16) __half g_kpvh[(size_t)R_*D_];
__device__ __align__(16) __half g_vth[(size_t)B_*D_*N_];
__device__ __align__(16) __half g_wexp[(size_t)B_*M_*N_];     // 128 MB: exp(l - m_tile)
__device__ __align__(16) __half g_sfact[NMT*B_*N_];           // exp(m_tile - cstat)
__device__ __align__(16) float  g_pmax[NMT*B_*N_], g_psum[NMT*B_*N_];
__device__ __align__(16) float  g_part[(size_t)B_*NSPLIT*M_*D_];

// ======================= small helpers ======================================
__device__ __forceinline__ uint32_t smem_u32(const void* p) {
    uint32_t a;
    asm("{ .reg .u64 t; cvta.to.shared.u64 t, %1; cvt.u32.u64 %0, t; }" : "=r"(a) : "l"(p));
    return a;
}
__device__ __forceinline__ void cp16(uint32_t dst, const void* src) {
    asm volatile("cp.async.cg.shared.global [%0], [%1], 16;" :: "r"(dst), "l"(src));
}
#define CP_COMMIT() asm volatile("cp.async.commit_group;" ::: "memory")
#define CP_WAIT0()  asm volatile("cp.async.wait_group 0;" ::: "memory")
#define CP_WAIT1()  asm volatile("cp.async.wait_group 1;" ::: "memory")

__device__ __forceinline__ void ldsm_x4(uint32_t& r0, uint32_t& r1, uint32_t& r2, uint32_t& r3,
                                        uint32_t addr) {
    asm volatile("ldmatrix.sync.aligned.m8n8.x4.shared.b16 {%0,%1,%2,%3}, [%4];"
                 : "=r"(r0), "=r"(r1), "=r"(r2), "=r"(r3) : "r"(addr));
}
__device__ __forceinline__ void mma16816(float* c, const uint32_t* a, uint32_t b0, uint32_t b1) {
    asm volatile(
        "mma.sync.aligned.m16n8k16.row.col.f32.f16.f16.f32 "
        "{%0,%1,%2,%3}, {%4,%5,%6,%7}, {%8,%9}, {%0,%1,%2,%3};"
        : "+f"(c[0]), "+f"(c[1]), "+f"(c[2]), "+f"(c[3])
        : "r"(a[0]), "r"(a[1]), "r"(a[2]), "r"(a[3]), "r"(b0), "r"(b1));
}

// swizzled byte offset in a 128-row x 32-half tile (64B rows)
__device__ __forceinline__ uint32_t sw(int row, int c16) {
    return (uint32_t)(row * 64 + ((c16 ^ ((row ^ (row >> 2)) & 3)) << 4));
}

// fast exp, FFMA-only, fp32-class (stats path). x <= 0.
__device__ __forceinline__ float fexp(float x) {
    x = fmaxf(x, -80.0f);
    float nf = fmaf(x, 1.4426950408889634f, 12582912.0f);
    int  i   = __float_as_int(nf) - 0x4B400000;
    float n  = nf - 12582912.0f;
    float f  = fmaf(n, -0.693145751953125f, x);
    f        = fmaf(n, -1.42860682030941723e-6f, f);
    float p = 1.3888889e-3f;
    p = fmaf(p, f, 8.3333333e-3f);
    p = fmaf(p, f, 4.1666668e-2f);
    p = fmaf(p, f, 1.6666667e-1f);
    p = fmaf(p, f, 5.0e-1f);
    p = fmaf(p, f, 1.0f);
    p = fmaf(p, f, 1.0f);
    return p * __int_as_float((i + 127) << 23);
}

// degree-4 exp, fp16-accuracy (4e-5 rel). x <= 0.
__device__ __forceinline__ float fexp4(float x) {
    x = fmaxf(x, -80.0f);
    float nf = fmaf(x, 1.4426950408889634f, 12582912.0f);
    int  i   = __float_as_int(nf) - 0x4B400000;
    float n  = nf - 12582912.0f;
    float f  = fmaf(n, -0.6931471805599453f, x);
    float p = 4.1666668e-2f;
    p = fmaf(p, f, 1.6666667e-1f);
    p = fmaf(p, f, 5.0e-1f);
    p = fmaf(p, f, 1.0f);
    p = fmaf(p, f, 1.0f);
    return p * __int_as_float((i + 127) << 23);
}

// ======================= 1-pass MMA over one 32-K sub-tile ===================
__device__ __forceinline__ void compute_sub(uint32_t sa, uint32_t sbb, int mw0, int nw0,
                                            float cacc[4][4][4], int lane) {
    int arow = lane & 15, asel = lane >> 4;
    int brow = (lane & 7) + ((lane >> 4) << 3), bsel = (lane >> 3) & 1;
#pragma unroll
    for (int ks = 0; ks < 2; ks++) {
        uint32_t ah[4][4], bh[2][4];
#pragma unroll
        for (int mi = 0; mi < 4; mi++)
            ldsm_x4(ah[mi][0], ah[mi][1], ah[mi][2], ah[mi][3],
                    sa + sw(mw0 + mi*16 + arow, ks*2 + asel));
#pragma unroll
        for (int nb = 0; nb < 2; nb++)
            ldsm_x4(bh[nb][0], bh[nb][1], bh[nb][2], bh[nb][3],
                    sbb + sw(nw0 + nb*16 + brow, ks*2 + bsel));
#pragma unroll
        for (int mi = 0; mi < 4; mi++)
#pragma unroll
            for (int nj = 0; nj < 4; nj++)
                mma16816(cacc[mi][nj], ah[mi], bh[nj>>1][(nj&1)*2], bh[nj>>1][(nj&1)*2+1]);
    }
}
// full 64-K stage: A0@0 A1@8192 B0@16384 B1@24576
__device__ __forceinline__ void compute_stage64(uint32_t sb, int mw0, int nw0,
                                                float cacc[4][4][4], int lane) {
    compute_sub(sb,        sb + 16384, mw0, nw0, cacc, lane);
    compute_sub(sb + 8192, sb + 24576, mw0, nw0, cacc, lane);
}

// cp.async staging of a 64-K stage (A + B), 256 threads, ld = D_
__device__ __forceinline__ void stage64(uint32_t sb,
                                        const __half* __restrict__ Ah, size_t ar0,
                                        const __half* __restrict__ Bh, size_t br0, int k0) {
    int t = threadIdx.x;
#pragma unroll
    for (int i = 0; i < 2; i++) {
        int c = t + 256*i;
        int row = c >> 2, c16 = c & 3;
        uint32_t so = sw(row, c16);
#pragma unroll
        for (int h = 0; h < 2; h++) {
            size_t ka = (size_t)k0 + h*32 + c16*8;
            cp16(sb + h*8192 + so,         Ah + (ar0 + row)*(size_t)D_ + ka);
            cp16(sb + 16384 + h*8192 + so, Bh + (br0 + row)*(size_t)D_ + ka);
        }
    }
}

// ======================= prep: cvt + weight transpose + positional ===========
#define NP2 ((size_t)R_*D_/2)
#define NV2 ((size_t)RQ_*D_/2)
#define NB_CVT ((unsigned)((NP2 + NV2 + 255)/256))
#define NB_WT  768u
#define NB_PV  ((unsigned)(R_/256))
__global__ void prep_kernel(const float* __restrict__ P, const float* __restrict__ VF,
                            const float* __restrict__ Wq, const float* __restrict__ Wk,
                            const float* __restrict__ Wv,
                            const float* __restrict__ p_xyz, const float* __restrict__ v_xyz,
                            const float* __restrict__ Wp1, const float* __restrict__ bp1,
                            const float* __restrict__ ln_w, const float* __restrict__ ln_b) {
    unsigned blk = blockIdx.x;
    if (blk < NB_CVT) {
        size_t i = (size_t)blk * 256 + threadIdx.x;
        const float* src; __half* hi; size_t j;
        if (i < NP2)            { src = P;  hi = g_ph;  j = i; }
        else if (i < NP2 + NV2) { src = VF; hi = g_vfh; j = i - NP2; }
        else return;
        float2 v = reinterpret_cast<const float2*>(src)[j];
        reinterpret_cast<__half2*>(hi)[j] =
            __halves2half2(__float2half_rn(v.x), __float2half_rn(v.y));
        return;
    }
    blk -= NB_CVT;
    if (blk < NB_WT) {
        int i = blk * 256 + threadIdx.x;   // 3*65536
        int w = i >> 16, rem = i & 65535;
        int d = rem >> 8, c = rem & 255;
        const float* W = (w == 0) ? Wq : (w == 1) ? Wk : Wv;
        __half* Th = (w == 0) ? g_wqT : (w == 1) ? g_wkT : g_wvT;
        Th[c*256 + d] = __float2half_rn(W[rem]);
        return;
    }
    blk -= NB_WT;
    {
        int idx = blk * 256 + threadIdx.x;
        int b = idx / N_;
        float d0 = fabsf(p_xyz[idx*3+0] - v_xyz[b*3+0]);
        float d1 = fabsf(p_xyz[idx*3+1] - v_xyz[b*3+1]);
        float d2 = fabsf(p_xyz[idx*3+2] - v_xyz[b*3+2]);
        float h0 = d0*Wp1[0] + d1*Wp1[3] + d2*Wp1[6] + bp1[0];
        float h1 = d0*Wp1[1] + d1*Wp1[4] + d2*Wp1[7] + bp1[1];
        float h2 = d0*Wp1[2] + d1*Wp1[5] + d2*Wp1[8] + bp1[2];
        float mu = (h0 + h1 + h2) * (1.0f/3.0f);
        float e0 = h0-mu, e1 = h1-mu, e2 = h2-mu;
        float inv = rsqrtf((e0*e0 + e1*e1 + e2*e2) * (1.0f/3.0f) + 1e-5f);
        g_r[idx*3+0] = fmaxf(e0*inv*ln_w[0] + ln_b[0], 0.0f);
        g_r[idx*3+1] = fmaxf(e1*inv*ln_w[1] + ln_b[1], 0.0f);
        g_r[idx*3+2] = fmaxf(e2*inv*ln_w[2] + ln_b[2], 0.0f);
    }
}

// ======================= fused projections (HMMA 1-pass, one launch) =========
// z=0: q = (vf@Wq + bq)/16 -> qh ; z=1: kpv = p@Wk + bk + pv -> kpvh ;
// z=2: v = p@Wv + bv -> TRANSPOSED fp16 store into g_vth
__global__ __launch_bounds__(256, 2)
void proj_mma_kernel(const float* __restrict__ bq, const float* __restrict__ bk,
                     const float* __restrict__ bv, const float* __restrict__ Wp2,
                     const float* __restrict__ bp2) {
    int mode = blockIdx.z;
    if (mode == 0 && blockIdx.y >= RQ_/128) return;
    extern __shared__ char dyn[];
    uint32_t sb = smem_u32(dyn);
    const __half *Xh, *WT; const float* bias;
    if (mode == 0)      { Xh = g_vfh; WT = g_wqT; bias = bq; }
    else if (mode == 1) { Xh = g_ph;  WT = g_wkT; bias = bk; }
    else                { Xh = g_ph;  WT = g_wvT; bias = bv; }

    size_t row0 = (size_t)blockIdx.y * 128;
    int c0 = blockIdx.x * 128;
    int lane = threadIdx.x & 31, wid = threadIdx.x >> 5;
    int mw0 = (wid >> 2) * 64, nw0 = (wid & 3) * 32;
    float cacc[4][4][4] = {};

    stage64(sb + 0*STAGE, Xh, row0, WT, (size_t)c0, 0);  CP_COMMIT();
    stage64(sb + 1*STAGE, Xh, row0, WT, (size_t)c0, 64); CP_COMMIT();
#pragma unroll
    for (int s = 0; s < 4; s++) {
        if (s < 3) CP_WAIT1(); else CP_WAIT0();
        __syncthreads();
        if (s + 2 < 4) {
            stage64(sb + ((s+2)%3)*STAGE, Xh, row0, WT, (size_t)c0, (s+2)*64);
            CP_COMMIT();
        }
        compute_stage64(sb + (s%3)*STAGE, mw0, nw0, cacc, lane);
    }

    int g = lane >> 2, tg = lane & 3;
    if (mode != 2) {
#pragma unroll
        for (int mi = 0; mi < 4; mi++) {
#pragma unroll
            for (int half_m = 0; half_m < 2; half_m++) {
                size_t r = row0 + mw0 + mi*16 + g + half_m*8;
                float q0 = 0.f, q1 = 0.f, q2 = 0.f;
                if (mode == 1) { q0 = g_r[r*3+0]; q1 = g_r[r*3+1]; q2 = g_r[r*3+2]; }
#pragma unroll
                for (int nj = 0; nj < 4; nj++) {
#pragma unroll
                    for (int e = 0; e < 2; e++) {
                        int c = c0 + nw0 + nj*8 + tg*2 + e;
                        float v = cacc[mi][nj][half_m*2 + e] + bias[c];
                        if (mode == 1) {
                            v += q0*Wp2[c] + q1*Wp2[D_+c] + q2*Wp2[2*D_+c] + bp2[c];
                            g_kpvh[r*D_+c] = __float2half_rn(v);
                        } else {
                            g_qh[r*D_+c] = __float2half_rn(v * 0.0625f);
                        }
                    }
                }
            }
        }
    } else {
        // v: transpose through smem (tile T[c_local][r_local], stride 132 halves)
        __syncthreads();
        __half* T = reinterpret_cast<__half*>(dyn);
#pragma unroll
        for (int mi = 0; mi < 4; mi++)
#pragma unroll
            for (int half_m = 0; half_m < 2; half_m++) {
                int rl = mw0 + mi*16 + g + half_m*8;
#pragma unroll
                for (int nj = 0; nj < 4; nj++)
#pragma unroll
                    for (int e = 0; e < 2; e++) {
                        int cl = nw0 + nj*8 + tg*2 + e;
                        float v = cacc[mi][nj][half_m*2 + e] + bias[c0 + cl];
                        T[cl*132 + rl] = __float2half_rn(v);
                    }
            }
        __syncthreads();
        int b = (int)(row0 >> 14);
        int nloc = (int)(row0 & (N_-1));
        int t = threadIdx.x;
        int cl = t >> 1, seg = t & 1;
        __half* dst = g_vth + (size_t)(b*D_ + c0 + cl)*N_ + nloc + seg*64;
        const __half* srcp = T + cl*132 + seg*64;
#pragma unroll
        for (int j = 0; j < 8; j++) {
            uint4 v4;
            v4.x = *reinterpret_cast<const uint32_t*>(srcp + j*8 + 0);
            v4.y = *reinterpret_cast<const uint32_t*>(srcp + j*8 + 2);
            v4.z = *reinterpret_cast<const uint32_t*>(srcp + j*8 + 4);
            v4.w = *reinterpret_cast<const uint32_t*>(srcp + j*8 + 6);
            *reinterpret_cast<uint4*>(dst + j*8) = v4;
        }
    }
}

// ======================= logits (HMMA 1-pass) -> fp16 tile-exp weights =======
__global__ __launch_bounds__(256, 2)
void logits_mma_kernel() {
    extern __shared__ char dyn[];
    uint32_t sb = smem_u32(dyn);
    int b = blockIdx.z;
    int n0 = blockIdx.x * 128, m0 = blockIdx.y * 128;
    size_t ar0 = (size_t)b*M_ + m0, br0 = (size_t)b*N_ + n0;
    int lane = threadIdx.x & 31, wid = threadIdx.x >> 5;
    int mw0 = (wid >> 2) * 64, nw0 = (wid & 3) * 32;
    float cacc[4][4][4] = {};

    stage64(sb + 0*STAGE, g_qh, ar0, g_kpvh, br0, 0);  CP_COMMIT();
    stage64(sb + 1*STAGE, g_qh, ar0, g_kpvh, br0, 64); CP_COMMIT();
#pragma unroll
    for (int s = 0; s < 4; s++) {
        if (s < 3) CP_WAIT1(); else CP_WAIT0();
        __syncthreads();
        if (s + 2 < 4) {
            stage64(sb + ((s+2)%3)*STAGE, g_qh, ar0, g_kpvh, br0, (s+2)*64);
            CP_COMMIT();
        }
        compute_stage64(sb + (s%3)*STAGE, mw0, nw0, cacc, lane);
    }

    int g = lane >> 2, tg = lane & 3;
    float* smax = reinterpret_cast<float*>(dyn);        // [2][128]
    float* ssum = smax + 256;                            // [2][128]
    __syncthreads();

    // phase 1: per-warp (64-row) column maxes
#pragma unroll
    for (int nj = 0; nj < 4; nj++) {
#pragma unroll
        for (int ec = 0; ec < 2; ec++) {
            float mx = -1e30f;
#pragma unroll
            for (int mi = 0; mi < 4; mi++) {
                mx = fmaxf(mx, cacc[mi][nj][ec]);
                mx = fmaxf(mx, cacc[mi][nj][2 + ec]);
            }
            mx = fmaxf(mx, __shfl_xor_sync(0xFFFFFFFFu, mx, 4));
            mx = fmaxf(mx, __shfl_xor_sync(0xFFFFFFFFu, mx, 8));
            mx = fmaxf(mx, __shfl_xor_sync(0xFFFFFFFFu, mx, 16));
            if (g == 0) {
                int nc = (wid & 3)*32 + nj*8 + tg*2 + ec;
                smax[(wid >> 2)*128 + nc] = mx;
            }
        }
    }
    __syncthreads();

    // phase 2: w = exp(l - tile_col_max) (deg-4), store fp16, accumulate sums
    __half* W = g_wexp + (size_t)b*M_*N_;
#pragma unroll
    for (int nj = 0; nj < 4; nj++) {
        int ncb = (wid & 3)*32 + nj*8 + tg*2;
        float mx0 = fmaxf(smax[ncb],     smax[128 + ncb]);
        float mx1 = fmaxf(smax[ncb + 1], smax[128 + ncb + 1]);
        float s0 = 0.0f, s1 = 0.0f;
#pragma unroll
        for (int mi = 0; mi < 4; mi++) {
#pragma unroll
            for (int hm = 0; hm < 2; hm++) {
                float w0 = fexp4(cacc[mi][nj][hm*2 + 0] - mx0);
                float w1 = fexp4(cacc[mi][nj][hm*2 + 1] - mx1);
                s0 += w0; s1 += w1;
                int m = m0 + mw0 + mi*16 + g + hm*8;
                *reinterpret_cast<__half2*>(&W[(size_t)m*N_ + n0 + ncb]) =
                    __halves2half2(__float2half_rn(w0), __float2half_rn(w1));
            }
        }
        s0 += __shfl_xor_sync(0xFFFFFFFFu, s0, 4);
        s0 += __shfl_xor_sync(0xFFFFFFFFu, s0, 8);
        s0 += __shfl_xor_sync(0xFFFFFFFFu, s0, 16);
        s1 += __shfl_xor_sync(0xFFFFFFFFu, s1, 4);
        s1 += __shfl_xor_sync(0xFFFFFFFFu, s1, 8);
        s1 += __shfl_xor_sync(0xFFFFFFFFu, s1, 16);
        if (g == 0) {
            ssum[(wid >> 2)*128 + ncb]     = s0;
            ssum[(wid >> 2)*128 + ncb + 1] = s1;
        }
    }
    __syncthreads();
    int t = threadIdx.x;
    if (t < 128) {
        int col = b*N_ + n0 + t;
        g_pmax[blockIdx.y*(B_*N_) + col] = fmaxf(smax[t], smax[128 + t]);
        g_psum[blockIdx.y*(B_*N_) + col] = ssum[t] + ssum[128 + t];
    }
}

// ======================= stats reduce -> per-tile scale factors ==============
// 4-way split per column: 4 lanes each handle 4 of 16 tiles, shfl merge.
__global__ void cstat_reduce_kernel() {
    int gid = blockIdx.x * blockDim.x + threadIdx.x;   // 0..4*B*N-1
    int col = gid >> 2, h = gid & 3;
    float pm[4];
    float mx = -1e30f, sum = 0.0f;
#pragma unroll
    for (int u = 0; u < 4; u++) {
        int ti = h*4 + u;
        float m2 = g_pmax[ti*(B_*N_) + col];
        float s2 = g_psum[ti*(B_*N_) + col];
        pm[u] = m2;
        if (m2 > mx) { sum = sum * fexp(mx - m2) + s2; mx = m2; }
        else         { sum += s2 * fexp(m2 - mx); }
    }
#pragma unroll
    for (int d = 1; d <= 2; d <<= 1) {
        float mo = __shfl_xor_sync(0xFFFFFFFFu, mx, d);
        float so = __shfl_xor_sync(0xFFFFFFFFu, sum, d);
        float mm = fmaxf(mx, mo);
        sum = sum * fexp(mx - mm) + so * fexp(mo - mm);
        mx = mm;
    }
    float cs = mx + __logf(sum);
#pragma unroll
    for (int u = 0; u < 4; u++)
        g_sfact[(h*4 + u)*(B_*N_) + col] = __float2half_rn(fexp(pm[u] - cs));
}

// ======================= weighted value (HMMA 1-pass, fp16 weights) ==========
__global__ __launch_bounds__(256, 2)
void wv_mma_kernel() {
    extern __shared__ char dyn[];
    uint32_t sb = smem_u32(dyn);
    int z = blockIdx.z, b = z >> 2, sp = z & 3;
    int d0 = blockIdx.x * 128, m0 = blockIdx.y * 128;
    int kbeg = sp * KR_;
    const __half* Wx = g_wexp + (size_t)b*M_*N_;
    const __half* SF = g_sfact + ((size_t)blockIdx.y*B_ + b)*N_;
    size_t br0 = (size_t)b*D_ + d0;
    int t = threadIdx.x, lane = t & 31, wid = t >> 5;
    int mw0 = (wid >> 2) * 64, nw0 = (wid & 3) * 32;
    float cacc[4][4][4] = {};

    int rows[2], c16s[2];
#pragma unroll
    for (int i = 0; i < 2; i++) { int c = t + 256*i; rows[i] = c >> 2; c16s[i] = c & 3; }

    // stage layout: W0@0 W1@8192 V0@16384 V1@24576
    uint4 wraw[2][2];
#pragma unroll
    for (int h = 0; h < 2; h++)
#pragma unroll
        for (int i = 0; i < 2; i++)
            wraw[h][i] = __ldg(reinterpret_cast<const uint4*>(
                Wx + (size_t)(m0 + rows[i])*N_ + kbeg + h*32 + c16s[i]*8));
#pragma unroll
    for (int st = 0; st < 2; st++) {
        uint32_t bufB = sb + st*STAGE;
#pragma unroll
        for (int h = 0; h < 2; h++)
#pragma unroll
            for (int i = 0; i < 2; i++) {
                uint32_t so = sw(rows[i], c16s[i]);
                size_t ka = (size_t)(kbeg + st*64 + h*32) + c16s[i]*8;
                cp16(bufB + 16384 + h*8192 + so, g_vth + (br0 + rows[i])*(size_t)N_ + ka);
            }
        CP_COMMIT();
    }

    const int NCH = KR_ / 64;   // 64
#pragma unroll 3
    for (int s = 0; s < NCH; s++) {
        uint32_t buf  = sb + (s%3)*STAGE;
        char*    bufp = dyn + (s%3)*STAGE;
        if (s < NCH-1) CP_WAIT1(); else CP_WAIT0();
        // transform + STS W(s): w = w_tile * sfact (half2 muls)
#pragma unroll
        for (int h = 0; h < 2; h++)
#pragma unroll
            for (int i = 0; i < 2; i++) {
                int kabs = kbeg + s*64 + h*32 + c16s[i]*8;
                uint4 sf4 = *reinterpret_cast<const uint4*>(SF + kabs);
                const __half2* wp = reinterpret_cast<const __half2*>(&wraw[h][i]);
                const __half2* spp = reinterpret_cast<const __half2*>(&sf4);
                uint4 outv;
                __half2* op = reinterpret_cast<__half2*>(&outv);
                op[0] = __hmul2(wp[0], spp[0]);
                op[1] = __hmul2(wp[1], spp[1]);
                op[2] = __hmul2(wp[2], spp[2]);
                op[3] = __hmul2(wp[3], spp[3]);
                uint32_t so = sw(rows[i], c16s[i]);
                *reinterpret_cast<uint4*>(bufp + h*8192 + so) = outv;
            }
        __syncthreads();
        if (s + 1 < NCH) {
            int kn = kbeg + (s+1)*64;
#pragma unroll
            for (int h = 0; h < 2; h++)
#pragma unroll
                for (int i = 0; i < 2; i++)
                    wraw[h][i] = __ldg(reinterpret_cast<const uint4*>(
                        Wx + (size_t)(m0 + rows[i])*N_ + kn + h*32 + c16s[i]*8));
        }
        if (s + 2 < NCH) {
            uint32_t nbuf = sb + ((s+2)%3)*STAGE;
            int kn2 = kbeg + (s+2)*64;
#pragma unroll
            for (int h = 0; h < 2; h++)
#pragma unroll
                for (int i = 0; i < 2; i++) {
                    uint32_t so = sw(rows[i], c16s[i]);
                    size_t ka = (size_t)(kn2 + h*32) + c16s[i]*8;
                    cp16(nbuf + 16384 + h*8192 + so, g_vth + (br0 + rows[i])*(size_t)N_ + ka);
                }
            CP_COMMIT();
        }
        compute_sub(buf,        buf + 16384, mw0, nw0, cacc, lane);
        compute_sub(buf + 8192, buf + 24576, mw0, nw0, cacc, lane);
    }

    int g = lane >> 2, tg = lane & 3;
    float* P = g_part + (size_t)z*M_*D_;
#pragma unroll
    for (int mi = 0; mi < 4; mi++)
#pragma unroll
        for (int nj = 0; nj < 4; nj++) {
            int m = m0 + mw0 + mi*16 + g;
            int d = d0 + nw0 + nj*8 + tg*2;
            float2 v0 = { cacc[mi][nj][0], cacc[mi][nj][1] };
            float2 v1 = { cacc[mi][nj][2], cacc[mi][nj][3] };
            *reinterpret_cast<float2*>(&P[(size_t)m*D_ + d])     = v0;
            *reinterpret_cast<float2*>(&P[(size_t)(m+8)*D_ + d]) = v1;
        }
}

// ======================= reduce + residual (2x ILP) ==========================
__global__ void reduce_kernel(const float* __restrict__ Vf, float* __restrict__ out) {
    int base = (blockIdx.x * blockDim.x + threadIdx.x) * 2;  // two float4 groups
#pragma unroll
    for (int u = 0; u < 2; u++) {
        int i4 = base + u;
        int row = i4 >> 6;
        int b = row >> 11;
        int mrow = row & (M_ - 1);
        int d4 = i4 & 63;
        float4 acc = __ldg(reinterpret_cast<const float4*>(Vf) + i4);
#pragma unroll
        for (int s = 0; s < NSPLIT; s++) {
            size_t pi = ((size_t)(b*NSPLIT + s)*M_ + mrow)*64 + d4;
            float4 p = __ldg(reinterpret_cast<const float4*>(g_part) + pi);
            acc.x += p.x; acc.y += p.y; acc.z += p.z; acc.w += p.w;
        }
        reinterpret_cast<float4*>(out)[i4] = acc;
    }
}

// ======================= launcher ============================================
extern "C" void kernel_launch(void* const* d_in, const int* in_sizes, int n_in,
                              void* d_out, int out_size) {
    const float* p_xyz      = (const float*)d_in[0];
    const float* v_xyz      = (const float*)d_in[1];
    const float* p_features = (const float*)d_in[2];
    const float* v_features = (const float*)d_in[3];
    const float* Wq  = (const float*)d_in[4];
    const float* bq  = (const float*)d_in[5];
    const float* Wk  = (const float*)d_in[6];
    const float* bk  = (const float*)d_in[7];
    const float* Wv  = (const float*)d_in[8];
    const float* bv  = (const float*)d_in[9];
    const float* Wp1 = (const float*)d_in[10];
    const float* bp1 = (const float*)d_in[11];
    const float* ln_w = (const float*)d_in[12];
    const float* ln_b = (const float*)d_in[13];
    const float* Wp2 = (const float*)d_in[14];
    const float* bp2 = (const float*)d_in[15];
    float* out = (float*)d_out;

    static int attr_done = 0;
    if (!attr_done) {
        cudaFuncSetAttribute(proj_mma_kernel,   cudaFuncAttributeMaxDynamicSharedMemorySize, DYN_SMEM);
        cudaFuncSetAttribute(logits_mma_kernel, cudaFuncAttributeMaxDynamicSharedMemorySize, DYN_SMEM);
        cudaFuncSetAttribute(wv_mma_kernel,     cudaFuncAttributeMaxDynamicSharedMemorySize, DYN_SMEM);
        attr_done = 1;
    }

    // [0] prep: fp16 converts + weight transpose + positional path
    prep_kernel<<<NB_CVT + NB_WT + NB_PV, 256>>>(p_features, v_features, Wq, Wk, Wv,
                                                 p_xyz, v_xyz, Wp1, bp1, ln_w, ln_b);
    // [1] fused projections q/k/v (1-pass, K64 stages) + fused V transpose
    proj_mma_kernel<<<dim3(2, R_/128, 3), 256, DYN_SMEM>>>(bq, bk, bv, Wp2, bp2);
    // [2] logits (1-pass, K64 stages) -> fp16 tile-exp weights + partial stats
    logits_mma_kernel<<<dim3(N_/128, M_/128, B_), 256, DYN_SMEM>>>();
    // [3] stats reduce -> per-tile fp16 scale factors (4-way split)
    cstat_reduce_kernel<<<(4*B_*N_)/256, 256>>>();
    // [4] weighted value (1-pass, K64 stages, fp16 weights * sfact, split-K=4)
    wv_mma_kernel<<<dim3(D_/128, M_/128, B_*NSPLIT), 256, DYN_SMEM>>>();
    // [5] reduce + residual (2x ILP)
    reduce_kernel<<<(RQ_*D_/8)/256, 256>>>(v_features, out);
}

// round 17
// speedup vs baseline: 1.0272x; 1.0272x over previous
#include <cuda_runtime.h>
#include <cuda_fp16.h>
#include <stdint.h>
#include <math.h>

#define B_  2
#define N_  16384
#define M_  2048
#define D_  256
#define R_  (B_*N_)
#define RQ_ (B_*M_)
#define NSPLIT 4
#define KR_ (N_/NSPLIT)          // 4096 contraction per wv split
#define NMT 16                   // number of m-tiles (M_/128)
#define STAGE 32768              // A0(8K) A1(8K) B0(8K) B1(8K)  (K-chunk 64)
#define DYN_SMEM (3*STAGE)       // 96 KB

// ======================= device scratch =====================================
__device__ __align__(16) float  g_r[R_*3];
__device__ __align__(16) __half g_ph [(size_t)R_*D_];
__device__ __align__(16) __half g_vfh[(size_t)RQ_*D_];
__device__ __align__(16) __half g_wqT[D_*D_], g_wkT[D_*D_], g_wvT[D_*D_];
__device__ __align__(16) __half g_qh [(size_t)RQ_*D_];        // pre-scaled by 1/16
__device__ __align__(16) __half g_kpvh[(size_t)R_*D_];
__device__ __align__(16) __half g_vth[(size_t)B_*D_*N_];
__device__ __align__(16) __half g_wexp[(size_t)B_*M_*N_];     // 128 MB: exp(l - m_tile)
__device__ __align__(16) __half g_sfact[NMT*B_*N_];           // exp(m_tile - cstat)
__device__ __align__(16) float  g_pmax[NMT*B_*N_], g_psum[NMT*B_*N_];
__device__ __align__(16) float  g_part[(size_t)B_*NSPLIT*M_*D_];

// ======================= small helpers ======================================
__device__ __forceinline__ uint32_t smem_u32(const void* p) {
    uint32_t a;
    asm("{ .reg .u64 t; cvta.to.shared.u64 t, %1; cvt.u32.u64 %0, t; }" : "=r"(a) : "l"(p));
    return a;
}
__device__ __forceinline__ void cp16(uint32_t dst, const void* src) {
    asm volatile("cp.async.cg.shared.global [%0], [%1], 16;" :: "r"(dst), "l"(src));
}
#define CP_COMMIT() asm volatile("cp.async.commit_group;" ::: "memory")
#define CP_WAIT0()  asm volatile("cp.async.wait_group 0;" ::: "memory")
#define CP_WAIT1()  asm volatile("cp.async.wait_group 1;" ::: "memory")

__device__ __forceinline__ void ldsm_x4(uint32_t& r0, uint32_t& r1, uint32_t& r2, uint32_t& r3,
                                        uint32_t addr) {
    asm volatile("ldmatrix.sync.aligned.m8n8.x4.shared.b16 {%0,%1,%2,%3}, [%4];"
                 : "=r"(r0), "=r"(r1), "=r"(r2), "=r"(r3) : "r"(addr));
}
__device__ __forceinline__ void mma16816(float* c, const uint32_t* a, uint32_t b0, uint32_t b1) {
    asm volatile(
        "mma.sync.aligned.m16n8k16.row.col.f32.f16.f16.f32 "
        "{%0,%1,%2,%3}, {%4,%5,%6,%7}, {%8,%9}, {%0,%1,%2,%3};"
        : "+f"(c[0]), "+f"(c[1]), "+f"(c[2]), "+f"(c[3])
        : "r"(a[0]), "r"(a[1]), "r"(a[2]), "r"(a[3]), "r"(b0), "r"(b1));
}

// swizzled byte offset in a 128-row x 32-half tile (64B rows)
__device__ __forceinline__ uint32_t sw(int row, int c16) {
    return (uint32_t)(row * 64 + ((c16 ^ ((row ^ (row >> 2)) & 3)) << 4));
}

// fast exp, FFMA-only, fp32-class (stats path). x <= 0.
__device__ __forceinline__ float fexp(float x) {
    x = fmaxf(x, -80.0f);
    float nf = fmaf(x, 1.4426950408889634f, 12582912.0f);
    int  i   = __float_as_int(nf) - 0x4B400000;
    float n  = nf - 12582912.0f;
    float f  = fmaf(n, -0.693145751953125f, x);
    f        = fmaf(n, -1.42860682030941723e-6f, f);
    float p = 1.3888889e-3f;
    p = fmaf(p, f, 8.3333333e-3f);
    p = fmaf(p, f, 4.1666668e-2f);
    p = fmaf(p, f, 1.6666667e-1f);
    p = fmaf(p, f, 5.0e-1f);
    p = fmaf(p, f, 1.0f);
    p = fmaf(p, f, 1.0f);
    return p * __int_as_float((i + 127) << 23);
}

// degree-4 exp, fp16-accuracy (4e-5 rel). x <= 0.
__device__ __forceinline__ float fexp4(float x) {
    x = fmaxf(x, -80.0f);
    float nf = fmaf(x, 1.4426950408889634f, 12582912.0f);
    int  i   = __float_as_int(nf) - 0x4B400000;
    float n  = nf - 12582912.0f;
    float f  = fmaf(n, -0.6931471805599453f, x);
    float p = 4.1666668e-2f;
    p = fmaf(p, f, 1.6666667e-1f);
    p = fmaf(p, f, 5.0e-1f);
    p = fmaf(p, f, 1.0f);
    p = fmaf(p, f, 1.0f);
    return p * __int_as_float((i + 127) << 23);
}

// ======================= 1-pass MMA over one 32-K sub-tile ===================
__device__ __forceinline__ void compute_sub(uint32_t sa, uint32_t sbb, int mw0, int nw0,
                                            float cacc[4][4][4], int lane) {
    int arow = lane & 15, asel = lane >> 4;
    int brow = (lane & 7) + ((lane >> 4) << 3), bsel = (lane >> 3) & 1;
#pragma unroll
    for (int ks = 0; ks < 2; ks++) {
        uint32_t ah[4][4], bh[2][4];
#pragma unroll
        for (int mi = 0; mi < 4; mi++)
            ldsm_x4(ah[mi][0], ah[mi][1], ah[mi][2], ah[mi][3],
                    sa + sw(mw0 + mi*16 + arow, ks*2 + asel));
#pragma unroll
        for (int nb = 0; nb < 2; nb++)
            ldsm_x4(bh[nb][0], bh[nb][1], bh[nb][2], bh[nb][3],
                    sbb + sw(nw0 + nb*16 + brow, ks*2 + bsel));
#pragma unroll
        for (int mi = 0; mi < 4; mi++)
#pragma unroll
            for (int nj = 0; nj < 4; nj++)
                mma16816(cacc[mi][nj], ah[mi], bh[nj>>1][(nj&1)*2], bh[nj>>1][(nj&1)*2+1]);
    }
}
// full 64-K stage: A0@0 A1@8192 B0@16384 B1@24576
__device__ __forceinline__ void compute_stage64(uint32_t sb, int mw0, int nw0,
                                                float cacc[4][4][4], int lane) {
    compute_sub(sb,        sb + 16384, mw0, nw0, cacc, lane);
    compute_sub(sb + 8192, sb + 24576, mw0, nw0, cacc, lane);
}

// cp.async staging of a 64-K stage (A + B), 256 threads, ld = D_
__device__ __forceinline__ void stage64(uint32_t sb,
                                        const __half* __restrict__ Ah, size_t ar0,
                                        const __half* __restrict__ Bh, size_t br0, int k0) {
    int t = threadIdx.x;
#pragma unroll
    for (int i = 0; i < 2; i++) {
        int c = t + 256*i;
        int row = c >> 2, c16 = c & 3;
        uint32_t so = sw(row, c16);
#pragma unroll
        for (int h = 0; h < 2; h++) {
            size_t ka = (size_t)k0 + h*32 + c16*8;
            cp16(sb + h*8192 + so,         Ah + (ar0 + row)*(size_t)D_ + ka);
            cp16(sb + 16384 + h*8192 + so, Bh + (br0 + row)*(size_t)D_ + ka);
        }
    }
}

// ======================= prep: cvt + weight transpose + positional ===========
#define NP2 ((size_t)R_*D_/2)
#define NV2 ((size_t)RQ_*D_/2)
#define NB_CVT ((unsigned)((NP2 + NV2 + 255)/256))
#define NB_WT  768u
#define NB_PV  ((unsigned)(R_/256))
__global__ void prep_kernel(const float* __restrict__ P, const float* __restrict__ VF,
                            const float* __restrict__ Wq, const float* __restrict__ Wk,
                            const float* __restrict__ Wv,
                            const float* __restrict__ p_xyz, const float* __restrict__ v_xyz,
                            const float* __restrict__ Wp1, const float* __restrict__ bp1,
                            const float* __restrict__ ln_w, const float* __restrict__ ln_b) {
    unsigned blk = blockIdx.x;
    if (blk < NB_CVT) {
        size_t i = (size_t)blk * 256 + threadIdx.x;
        const float* src; __half* hi; size_t j;
        if (i < NP2)            { src = P;  hi = g_ph;  j = i; }
        else if (i < NP2 + NV2) { src = VF; hi = g_vfh; j = i - NP2; }
        else return;
        float2 v = reinterpret_cast<const float2*>(src)[j];
        reinterpret_cast<__half2*>(hi)[j] =
            __halves2half2(__float2half_rn(v.x), __float2half_rn(v.y));
        return;
    }
    blk -= NB_CVT;
    if (blk < NB_WT) {
        int i = blk * 256 + threadIdx.x;   // 3*65536
        int w = i >> 16, rem = i & 65535;
        int d = rem >> 8, c = rem & 255;
        const float* W = (w == 0) ? Wq : (w == 1) ? Wk : Wv;
        __half* Th = (w == 0) ? g_wqT : (w == 1) ? g_wkT : g_wvT;
        Th[c*256 + d] = __float2half_rn(W[rem]);
        return;
    }
    blk -= NB_WT;
    {
        int idx = blk * 256 + threadIdx.x;
        int b = idx / N_;
        float d0 = fabsf(p_xyz[idx*3+0] - v_xyz[b*3+0]);
        float d1 = fabsf(p_xyz[idx*3+1] - v_xyz[b*3+1]);
        float d2 = fabsf(p_xyz[idx*3+2] - v_xyz[b*3+2]);
        float h0 = d0*Wp1[0] + d1*Wp1[3] + d2*Wp1[6] + bp1[0];
        float h1 = d0*Wp1[1] + d1*Wp1[4] + d2*Wp1[7] + bp1[1];
        float h2 = d0*Wp1[2] + d1*Wp1[5] + d2*Wp1[8] + bp1[2];
        float mu = (h0 + h1 + h2) * (1.0f/3.0f);
        float e0 = h0-mu, e1 = h1-mu, e2 = h2-mu;
        float inv = rsqrtf((e0*e0 + e1*e1 + e2*e2) * (1.0f/3.0f) + 1e-5f);
        g_r[idx*3+0] = fmaxf(e0*inv*ln_w[0] + ln_b[0], 0.0f);
        g_r[idx*3+1] = fmaxf(e1*inv*ln_w[1] + ln_b[1], 0.0f);
        g_r[idx*3+2] = fmaxf(e2*inv*ln_w[2] + ln_b[2], 0.0f);
    }
}

// ======================= fused projections (HMMA 1-pass, one launch) =========
// z=0: q = (vf@Wq + bq)/16 -> qh ; z=1: kpv = p@Wk + bk + pv -> kpvh ;
// z=2: v = p@Wv + bv -> TRANSPOSED fp16 store into g_vth
__global__ __launch_bounds__(256, 2)
void proj_mma_kernel(const float* __restrict__ bq, const float* __restrict__ bk,
                     const float* __restrict__ bv, const float* __restrict__ Wp2,
                     const float* __restrict__ bp2) {
    int mode = blockIdx.z;
    if (mode == 0 && blockIdx.y >= RQ_/128) return;
    extern __shared__ char dyn[];
    uint32_t sb = smem_u32(dyn);
    const __half *Xh, *WT; const float* bias;
    if (mode == 0)      { Xh = g_vfh; WT = g_wqT; bias = bq; }
    else if (mode == 1) { Xh = g_ph;  WT = g_wkT; bias = bk; }
    else                { Xh = g_ph;  WT = g_wvT; bias = bv; }

    size_t row0 = (size_t)blockIdx.y * 128;
    int c0 = blockIdx.x * 128;
    int lane = threadIdx.x & 31, wid = threadIdx.x >> 5;
    int mw0 = (wid >> 2) * 64, nw0 = (wid & 3) * 32;
    float cacc[4][4][4] = {};

    stage64(sb + 0*STAGE, Xh, row0, WT, (size_t)c0, 0);  CP_COMMIT();
    stage64(sb + 1*STAGE, Xh, row0, WT, (size_t)c0, 64); CP_COMMIT();
#pragma unroll 1
    for (int s = 0; s < 4; s++) {
        if (s < 3) CP_WAIT1(); else CP_WAIT0();
        __syncthreads();
        if (s + 2 < 4) {
            stage64(sb + ((s+2)%3)*STAGE, Xh, row0, WT, (size_t)c0, (s+2)*64);
            CP_COMMIT();
        }
        compute_stage64(sb + (s%3)*STAGE, mw0, nw0, cacc, lane);
    }

    int g = lane >> 2, tg = lane & 3;
    if (mode != 2) {
#pragma unroll
        for (int mi = 0; mi < 4; mi++) {
#pragma unroll
            for (int half_m = 0; half_m < 2; half_m++) {
                size_t r = row0 + mw0 + mi*16 + g + half_m*8;
                float q0 = 0.f, q1 = 0.f, q2 = 0.f;
                if (mode == 1) { q0 = g_r[r*3+0]; q1 = g_r[r*3+1]; q2 = g_r[r*3+2]; }
#pragma unroll
                for (int nj = 0; nj < 4; nj++) {
#pragma unroll
                    for (int e = 0; e < 2; e++) {
                        int c = c0 + nw0 + nj*8 + tg*2 + e;
                        float v = cacc[mi][nj][half_m*2 + e] + bias[c];
                        if (mode == 1) {
                            v += q0*Wp2[c] + q1*Wp2[D_+c] + q2*Wp2[2*D_+c] + bp2[c];
                            g_kpvh[r*D_+c] = __float2half_rn(v);
                        } else {
                            g_qh[r*D_+c] = __float2half_rn(v * 0.0625f);
                        }
                    }
                }
            }
        }
    } else {
        // v: transpose through smem (tile T[c_local][r_local], stride 132 halves)
        __syncthreads();
        __half* T = reinterpret_cast<__half*>(dyn);
#pragma unroll
        for (int mi = 0; mi < 4; mi++)
#pragma unroll
            for (int half_m = 0; half_m < 2; half_m++) {
                int rl = mw0 + mi*16 + g + half_m*8;
#pragma unroll
                for (int nj = 0; nj < 4; nj++)
#pragma unroll
                    for (int e = 0; e < 2; e++) {
                        int cl = nw0 + nj*8 + tg*2 + e;
                        float v = cacc[mi][nj][half_m*2 + e] + bias[c0 + cl];
                        T[cl*132 + rl] = __float2half_rn(v);
                    }
            }
        __syncthreads();
        int b = (int)(row0 >> 14);
        int nloc = (int)(row0 & (N_-1));
        int t = threadIdx.x;
        int cl = t >> 1, seg = t & 1;
        __half* dst = g_vth + (size_t)(b*D_ + c0 + cl)*N_ + nloc + seg*64;
        const __half* srcp = T + cl*132 + seg*64;
#pragma unroll
        for (int j = 0; j < 8; j++) {
            uint4 v4;
            v4.x = *reinterpret_cast<const uint32_t*>(srcp + j*8 + 0);
            v4.y = *reinterpret_cast<const uint32_t*>(srcp + j*8 + 2);
            v4.z = *reinterpret_cast<const uint32_t*>(srcp + j*8 + 4);
            v4.w = *reinterpret_cast<const uint32_t*>(srcp + j*8 + 6);
            *reinterpret_cast<uint4*>(dst + j*8) = v4;
        }
    }
}

// ======================= logits (HMMA 1-pass) -> fp16 tile-exp weights =======
__global__ __launch_bounds__(256, 2)
void logits_mma_kernel() {
    extern __shared__ char dyn[];
    uint32_t sb = smem_u32(dyn);
    int b = blockIdx.z;
    int n0 = blockIdx.x * 128, m0 = blockIdx.y * 128;
    size_t ar0 = (size_t)b*M_ + m0, br0 = (size_t)b*N_ + n0;
    int lane = threadIdx.x & 31, wid = threadIdx.x >> 5;
    int mw0 = (wid >> 2) * 64, nw0 = (wid & 3) * 32;
    float cacc[4][4][4] = {};

    stage64(sb + 0*STAGE, g_qh, ar0, g_kpvh, br0, 0);  CP_COMMIT();
    stage64(sb + 1*STAGE, g_qh, ar0, g_kpvh, br0, 64); CP_COMMIT();
#pragma unroll 1
    for (int s = 0; s < 4; s++) {
        if (s < 3) CP_WAIT1(); else CP_WAIT0();
        __syncthreads();
        if (s + 2 < 4) {
            stage64(sb + ((s+2)%3)*STAGE, g_qh, ar0, g_kpvh, br0, (s+2)*64);
            CP_COMMIT();
        }
        compute_stage64(sb + (s%3)*STAGE, mw0, nw0, cacc, lane);
    }

    int g = lane >> 2, tg = lane & 3;
    float* smax = reinterpret_cast<float*>(dyn);        // [2][128]
    float* ssum = smax + 256;                            // [2][128]
    __syncthreads();

    // phase 1: per-warp (64-row) column maxes
#pragma unroll
    for (int nj = 0; nj < 4; nj++) {
#pragma unroll
        for (int ec = 0; ec < 2; ec++) {
            float mx = -1e30f;
#pragma unroll
            for (int mi = 0; mi < 4; mi++) {
                mx = fmaxf(mx, cacc[mi][nj][ec]);
                mx = fmaxf(mx, cacc[mi][nj][2 + ec]);
            }
            mx = fmaxf(mx, __shfl_xor_sync(0xFFFFFFFFu, mx, 4));
            mx = fmaxf(mx, __shfl_xor_sync(0xFFFFFFFFu, mx, 8));
            mx = fmaxf(mx, __shfl_xor_sync(0xFFFFFFFFu, mx, 16));
            if (g == 0) {
                int nc = (wid & 3)*32 + nj*8 + tg*2 + ec;
                smax[(wid >> 2)*128 + nc] = mx;
            }
        }
    }
    __syncthreads();

    // phase 2: w = exp(l - tile_col_max) (deg-4), store fp16, accumulate sums
    __half* W = g_wexp + (size_t)b*M_*N_;
#pragma unroll
    for (int nj = 0; nj < 4; nj++) {
        int ncb = (wid & 3)*32 + nj*8 + tg*2;
        float mx0 = fmaxf(smax[ncb],     smax[128 + ncb]);
        float mx1 = fmaxf(smax[ncb + 1], smax[128 + ncb + 1]);
        float s0 = 0.0f, s1 = 0.0f;
#pragma unroll
        for (int mi = 0; mi < 4; mi++) {
#pragma unroll
            for (int hm = 0; hm < 2; hm++) {
                float w0 = fexp4(cacc[mi][nj][hm*2 + 0] - mx0);
                float w1 = fexp4(cacc[mi][nj][hm*2 + 1] - mx1);
                s0 += w0; s1 += w1;
                int m = m0 + mw0 + mi*16 + g + hm*8;
                *reinterpret_cast<__half2*>(&W[(size_t)m*N_ + n0 + ncb]) =
                    __halves2half2(__float2half_rn(w0), __float2half_rn(w1));
            }
        }
        s0 += __shfl_xor_sync(0xFFFFFFFFu, s0, 4);
        s0 += __shfl_xor_sync(0xFFFFFFFFu, s0, 8);
        s0 += __shfl_xor_sync(0xFFFFFFFFu, s0, 16);
        s1 += __shfl_xor_sync(0xFFFFFFFFu, s1, 4);
        s1 += __shfl_xor_sync(0xFFFFFFFFu, s1, 8);
        s1 += __shfl_xor_sync(0xFFFFFFFFu, s1, 16);
        if (g == 0) {
            ssum[(wid >> 2)*128 + ncb]     = s0;
            ssum[(wid >> 2)*128 + ncb + 1] = s1;
        }
    }
    __syncthreads();
    int t = threadIdx.x;
    if (t < 128) {
        int col = b*N_ + n0 + t;
        g_pmax[blockIdx.y*(B_*N_) + col] = fmaxf(smax[t], smax[128 + t]);
        g_psum[blockIdx.y*(B_*N_) + col] = ssum[t] + ssum[128 + t];
    }
}

// ======================= stats reduce -> per-tile scale factors ==============
// 4-way split per column: 4 lanes each handle 4 of 16 tiles, shfl merge.
__global__ void cstat_reduce_kernel() {
    int gid = blockIdx.x * blockDim.x + threadIdx.x;   // 0..4*B*N-1
    int col = gid >> 2, h = gid & 3;
    float pm[4];
    float mx = -1e30f, sum = 0.0f;
#pragma unroll
    for (int u = 0; u < 4; u++) {
        int ti = h*4 + u;
        float m2 = g_pmax[ti*(B_*N_) + col];
        float s2 = g_psum[ti*(B_*N_) + col];
        pm[u] = m2;
        if (m2 > mx) { sum = sum * fexp(mx - m2) + s2; mx = m2; }
        else         { sum += s2 * fexp(m2 - mx); }
    }
#pragma unroll
    for (int d = 1; d <= 2; d <<= 1) {
        float mo = __shfl_xor_sync(0xFFFFFFFFu, mx, d);
        float so = __shfl_xor_sync(0xFFFFFFFFu, sum, d);
        float mm = fmaxf(mx, mo);
        sum = sum * fexp(mx - mm) + so * fexp(mo - mm);
        mx = mm;
    }
    float cs = mx + __logf(sum);
#pragma unroll
    for (int u = 0; u < 4; u++)
        g_sfact[(h*4 + u)*(B_*N_) + col] = __float2half_rn(fexp(pm[u] - cs));
}

// ======================= weighted value (HMMA 1-pass, fp16 weights) ==========
__global__ __launch_bounds__(256, 2)
void wv_mma_kernel() {
    extern __shared__ char dyn[];
    uint32_t sb = smem_u32(dyn);
    int z = blockIdx.z, b = z >> 2, sp = z & 3;
    int d0 = blockIdx.x * 128, m0 = blockIdx.y * 128;
    int kbeg = sp * KR_;
    const __half* Wx = g_wexp + (size_t)b*M_*N_;
    const __half* SF = g_sfact + ((size_t)blockIdx.y*B_ + b)*N_;
    size_t br0 = (size_t)b*D_ + d0;
    int t = threadIdx.x, lane = t & 31, wid = t >> 5;
    int mw0 = (wid >> 2) * 64, nw0 = (wid & 3) * 32;
    float cacc[4][4][4] = {};

    int rows[2], c16s[2];
#pragma unroll
    for (int i = 0; i < 2; i++) { int c = t + 256*i; rows[i] = c >> 2; c16s[i] = c & 3; }

    // stage layout: W0@0 W1@8192 V0@16384 V1@24576
    uint4 wraw[2][2];
#pragma unroll
    for (int h = 0; h < 2; h++)
#pragma unroll
        for (int i = 0; i < 2; i++)
            wraw[h][i] = __ldg(reinterpret_cast<const uint4*>(
                Wx + (size_t)(m0 + rows[i])*N_ + kbeg + h*32 + c16s[i]*8));
#pragma unroll
    for (int st = 0; st < 2; st++) {
        uint32_t bufB = sb + st*STAGE;
#pragma unroll
        for (int h = 0; h < 2; h++)
#pragma unroll
            for (int i = 0; i < 2; i++) {
                uint32_t so = sw(rows[i], c16s[i]);
                size_t ka = (size_t)(kbeg + st*64 + h*32) + c16s[i]*8;
                cp16(bufB + 16384 + h*8192 + so, g_vth + (br0 + rows[i])*(size_t)N_ + ka);
            }
        CP_COMMIT();
    }

    const int NCH = KR_ / 64;   // 64
#pragma unroll 2
    for (int s = 0; s < NCH; s++) {
        uint32_t buf  = sb + (s%3)*STAGE;
        char*    bufp = dyn + (s%3)*STAGE;
        if (s < NCH-1) CP_WAIT1(); else CP_WAIT0();
        // transform + STS W(s): w = w_tile * sfact (half2 muls)
#pragma unroll
        for (int h = 0; h < 2; h++)
#pragma unroll
            for (int i = 0; i < 2; i++) {
                int kabs = kbeg + s*64 + h*32 + c16s[i]*8;
                uint4 sf4 = *reinterpret_cast<const uint4*>(SF + kabs);
                const __half2* wp = reinterpret_cast<const __half2*>(&wraw[h][i]);
                const __half2* spp = reinterpret_cast<const __half2*>(&sf4);
                uint4 outv;
                __half2* op = reinterpret_cast<__half2*>(&outv);
                op[0] = __hmul2(wp[0], spp[0]);
                op[1] = __hmul2(wp[1], spp[1]);
                op[2] = __hmul2(wp[2], spp[2]);
                op[3] = __hmul2(wp[3], spp[3]);
                uint32_t so = sw(rows[i], c16s[i]);
                *reinterpret_cast<uint4*>(bufp + h*8192 + so) = outv;
            }
        __syncthreads();
        if (s + 1 < NCH) {
            int kn = kbeg + (s+1)*64;
#pragma unroll
            for (int h = 0; h < 2; h++)
#pragma unroll
                for (int i = 0; i < 2; i++)
                    wraw[h][i] = __ldg(reinterpret_cast<const uint4*>(
                        Wx + (size_t)(m0 + rows[i])*N_ + kn + h*32 + c16s[i]*8));
        }
        if (s + 2 < NCH) {
            uint32_t nbuf = sb + ((s+2)%3)*STAGE;
            int kn2 = kbeg + (s+2)*64;
#pragma unroll
            for (int h = 0; h < 2; h++)
#pragma unroll
                for (int i = 0; i < 2; i++) {
                    uint32_t so = sw(rows[i], c16s[i]);
                    size_t ka = (size_t)(kn2 + h*32) + c16s[i]*8;
                    cp16(nbuf + 16384 + h*8192 + so, g_vth + (br0 + rows[i])*(size_t)N_ + ka);
                }
            CP_COMMIT();
        }
        compute_sub(buf,        buf + 16384, mw0, nw0, cacc, lane);
        compute_sub(buf + 8192, buf + 24576, mw0, nw0, cacc, lane);
    }

    int g = lane >> 2, tg = lane & 3;
    float* P = g_part + (size_t)z*M_*D_;
#pragma unroll
    for (int mi = 0; mi < 4; mi++)
#pragma unroll
        for (int nj = 0; nj < 4; nj++) {
            int m = m0 + mw0 + mi*16 + g;
            int d = d0 + nw0 + nj*8 + tg*2;
            float2 v0 = { cacc[mi][nj][0], cacc[mi][nj][1] };
            float2 v1 = { cacc[mi][nj][2], cacc[mi][nj][3] };
            *reinterpret_cast<float2*>(&P[(size_t)m*D_ + d])     = v0;
            *reinterpret_cast<float2*>(&P[(size_t)(m+8)*D_ + d]) = v1;
        }
}

// ======================= reduce + residual (2x ILP) ==========================
__global__ void reduce_kernel(const float* __restrict__ Vf, float* __restrict__ out) {
    int base = (blockIdx.x * blockDim.x + threadIdx.x) * 2;  // two float4 groups
#pragma unroll
    for (int u = 0; u < 2; u++) {
        int i4 = base + u;
        int row = i4 >> 6;
        int b = row >> 11;
        int mrow = row & (M_ - 1);
        int d4 = i4 & 63;
        float4 acc = __ldg(reinterpret_cast<const float4*>(Vf) + i4);
#pragma unroll
        for (int s = 0; s < NSPLIT; s++) {
            size_t pi = ((size_t)(b*NSPLIT + s)*M_ + mrow)*64 + d4;
            float4 p = __ldg(reinterpret_cast<const float4*>(g_part) + pi);
            acc.x += p.x; acc.y += p.y; acc.z += p.z; acc.w += p.w;
        }
        reinterpret_cast<float4*>(out)[i4] = acc;
    }
}

// ======================= launcher ============================================
extern "C" void kernel_launch(void* const* d_in, const int* in_sizes, int n_in,
                              void* d_out, int out_size) {
    const float* p_xyz      = (const float*)d_in[0];
    const float* v_xyz      = (const float*)d_in[1];
    const float* p_features = (const float*)d_in[2];
    const float* v_features = (const float*)d_in[3];
    const float* Wq  = (const float*)d_in[4];
    const float* bq  = (const float*)d_in[5];
    const float* Wk  = (const float*)d_in[6];
    const float* bk  = (const float*)d_in[7];
    const float* Wv  = (const float*)d_in[8];
    const float* bv  = (const float*)d_in[9];
    const float* Wp1 = (const float*)d_in[10];
    const float* bp1 = (const float*)d_in[11];
    const float* ln_w = (const float*)d_in[12];
    const float* ln_b = (const float*)d_in[13];
    const float* Wp2 = (const float*)d_in[14];
    const float* bp2 = (const float*)d_in[15];
    float* out = (float*)d_out;

    static int attr_done = 0;
    if (!attr_done) {
        cudaFuncSetAttribute(proj_mma_kernel,   cudaFuncAttributeMaxDynamicSharedMemorySize, DYN_SMEM);
        cudaFuncSetAttribute(logits_mma_kernel, cudaFuncAttributeMaxDynamicSharedMemorySize, DYN_SMEM);
        cudaFuncSetAttribute(wv_mma_kernel,     cudaFuncAttributeMaxDynamicSharedMemorySize, DYN_SMEM);
        attr_done = 1;
    }

    // [0] prep: fp16 converts + weight transpose + positional path
    prep_kernel<<<NB_CVT + NB_WT + NB_PV, 256>>>(p_features, v_features, Wq, Wk, Wv,
                                                 p_xyz, v_xyz, Wp1, bp1, ln_w, ln_b);
    // [1] fused projections q/k/v (1-pass, K64 stages) + fused V transpose
    proj_mma_kernel<<<dim3(2, R_/128, 3), 256, DYN_SMEM>>>(bq, bk, bv, Wp2, bp2);
    // [2] logits (1-pass, K64 stages) -> fp16 tile-exp weights + partial stats
    logits_mma_kernel<<<dim3(N_/128, M_/128, B_), 256, DYN_SMEM>>>();
    // [3] stats reduce -> per-tile fp16 scale factors (4-way split)
    cstat_reduce_kernel<<<(4*B_*N_)/256, 256>>>();
    // [4] weighted value (1-pass, K64 stages, fp16 weights * sfact, split-K=4)
    wv_mma_kernel<<<dim3(D_/128, M_/128, B_*NSPLIT), 256, DYN_SMEM>>>();
    // [5] reduce + residual (2x ILP)
    reduce_kernel<<<(RQ_*D_/8)/256, 256>>>(v_features, out);
}